// round 1
// baseline (speedup 1.0000x reference)
#include <cuda_runtime.h>
#include <cuda_bf16.h>

// Problem shapes (fixed by the dataset)
#define BB   128            // batch
#define NN   256            // boxes per batch
#define HH   256
#define WW   256
#define HW   (HH * WW)      // 65536

// Scratch (device globals — no allocations allowed)
__device__ float g_partial_sum[BB];
__device__ int   g_partial_cnt[BB];

// One block per batch b, one thread per box n.
__global__ __launch_bounds__(NN) void iou_loss_compute(
    const float* __restrict__ out,      // [B, 2, H, W]
    const float* __restrict__ target,   // [B, N, 2]
    const int*   __restrict__ ind,      // [B, N]
    const int*   __restrict__ mask)     // [B, N] (bool promoted to int32)
{
    const int b   = blockIdx.x;
    const int n   = threadIdx.x;
    const int idx = b * NN + n;

    float loss = 0.0f;
    int   m    = (mask[idx] != 0) ? 1 : 0;

    if (m) {
        const int id = ind[idx];
        const float x = (float)(id % WW);
        const float y = (float)(id / WW);

        // gather detection: out[b, 0, y, x], out[b, 1, y, x]
        const float* base = out + (size_t)b * 2 * HW;
        const float dx = base[id];        // channel 0 (w)
        const float dy = base[HW + id];   // channel 1 (h)

        const float tx = target[idx * 2 + 0];
        const float ty = target[idx * 2 + 1];

        // trunc toward zero, matching torch .int() / jnp.trunc
        const float gx = truncf(x - tx * 0.5f);
        const float gy = truncf(y - ty * 0.5f);
        const float px = truncf(x - dx * 0.5f);
        const float py = truncf(y - dy * 0.5f);

        // xywh center convention
        const float g_x1 = gx - tx * 0.5f, g_x2 = gx + tx * 0.5f;
        const float g_y1 = gy - ty * 0.5f, g_y2 = gy + ty * 0.5f;
        const float d_x1 = px - dx * 0.5f, d_x2 = px + dx * 0.5f;
        const float d_y1 = py - dy * 0.5f, d_y2 = py + dy * 0.5f;

        const float iw = fmaxf(fminf(g_x2, d_x2) - fmaxf(g_x1, d_x1), 0.0f);
        const float ih = fmaxf(fminf(g_y2, d_y2) - fmaxf(g_y1, d_y1), 0.0f);
        const float inter = iw * ih;

        const float w1 = g_x2 - g_x1, h1 = g_y2 - g_y1;
        const float w2 = d_x2 - d_x1, h2 = d_y2 - d_y1;
        const float uni = w1 * h1 + 1e-16f + w2 * h2 - inter;

        loss = 1.0f - inter / uni;
    }

    // warp reduce (fixed, deterministic order)
    #pragma unroll
    for (int off = 16; off > 0; off >>= 1) {
        loss += __shfl_down_sync(0xFFFFFFFFu, loss, off);
        m    += __shfl_down_sync(0xFFFFFFFFu, m,    off);
    }

    __shared__ float s_sum[NN / 32];
    __shared__ int   s_cnt[NN / 32];
    const int lane = n & 31, warp = n >> 5;
    if (lane == 0) { s_sum[warp] = loss; s_cnt[warp] = m; }
    __syncthreads();

    if (warp == 0) {
        float v = (lane < NN / 32) ? s_sum[lane] : 0.0f;
        int   c = (lane < NN / 32) ? s_cnt[lane] : 0;
        #pragma unroll
        for (int off = 4; off > 0; off >>= 1) {
            v += __shfl_down_sync(0xFFFFFFFFu, v, off);
            c += __shfl_down_sync(0xFFFFFFFFu, c, off);
        }
        if (lane == 0) { g_partial_sum[b] = v; g_partial_cnt[b] = c; }
    }
}

// Deterministic final reduction of 128 partials.
__global__ __launch_bounds__(128) void iou_loss_finalize(float* __restrict__ d_out)
{
    const int t = threadIdx.x;
    float v = g_partial_sum[t];
    int   c = g_partial_cnt[t];

    #pragma unroll
    for (int off = 16; off > 0; off >>= 1) {
        v += __shfl_down_sync(0xFFFFFFFFu, v, off);
        c += __shfl_down_sync(0xFFFFFFFFu, c, off);
    }

    __shared__ float s_sum[4];
    __shared__ int   s_cnt[4];
    const int lane = t & 31, warp = t >> 5;
    if (lane == 0) { s_sum[warp] = v; s_cnt[warp] = c; }
    __syncthreads();

    if (t == 0) {
        float total = s_sum[0] + s_sum[1] + s_sum[2] + s_sum[3];
        int   cnt   = s_cnt[0] + s_cnt[1] + s_cnt[2] + s_cnt[3];
        d_out[0] = total / (4.0f * (float)cnt + 0.0001f);
    }
}

extern "C" void kernel_launch(void* const* d_in, const int* in_sizes, int n_in,
                              void* d_out, int out_size)
{
    const float* out_map = (const float*)d_in[0];  // [128,2,256,256] f32
    const float* target  = (const float*)d_in[1];  // [128,256,2]     f32
    const int*   ind     = (const int*)  d_in[2];  // [128,256]       i32
    const int*   mask    = (const int*)  d_in[3];  // [128,256]       i32 (bool)
    float*       outp    = (float*)d_out;

    iou_loss_compute<<<BB, NN>>>(out_map, target, ind, mask);
    iou_loss_finalize<<<1, 128>>>(outp);
}

// round 2
// speedup vs baseline: 1.0188x; 1.0188x over previous
#include <cuda_runtime.h>
#include <cuda_bf16.h>

// Problem shapes (fixed by the dataset)
#define BB   128            // batch
#define NN   256            // boxes per batch
#define HH   256
#define WW   256
#define HW   (HH * WW)      // 65536

// Scratch (device globals — no allocations allowed). Zero-initialized at load;
// g_arrive is reset by the last block each call so graph replays are identical.
__device__ float g_partial_sum[BB];
__device__ int   g_partial_cnt[BB];
__device__ int   g_arrive = 0;

// One block per batch b, one thread per box n. Single fused launch.
__global__ __launch_bounds__(NN) void iou_loss_fused(
    const float* __restrict__ out,      // [B, 2, H, W]
    const float* __restrict__ target,   // [B, N, 2]
    const int*   __restrict__ ind,      // [B, N]
    const int*   __restrict__ mask,     // [B, N] (bool promoted to int32)
    float*       __restrict__ d_out)
{
    const int b   = blockIdx.x;
    const int n   = threadIdx.x;
    const int idx = b * NN + n;

    // Front-batch all independent loads (MLP overlaps DRAM latency).
    const int   mk = mask[idx];
    const int   id = ind[idx];
    const float tx = target[idx * 2 + 0];
    const float ty = target[idx * 2 + 1];

    float loss = 0.0f;
    int   m    = (mk != 0) ? 1 : 0;

    if (m) {
        const float x = (float)(id & (WW - 1));
        const float y = (float)(id >> 8);

        // gather detection: out[b, 0, y, x], out[b, 1, y, x]
        const float* base = out + (size_t)b * 2 * HW;
        const float dx = base[id];        // channel 0
        const float dy = base[HW + id];   // channel 1

        // trunc toward zero, matching torch .int() / jnp.trunc
        const float gx = truncf(x - tx * 0.5f);
        const float gy = truncf(y - ty * 0.5f);
        const float px = truncf(x - dx * 0.5f);
        const float py = truncf(y - dy * 0.5f);

        const float g_x1 = gx - tx * 0.5f, g_x2 = gx + tx * 0.5f;
        const float g_y1 = gy - ty * 0.5f, g_y2 = gy + ty * 0.5f;
        const float d_x1 = px - dx * 0.5f, d_x2 = px + dx * 0.5f;
        const float d_y1 = py - dy * 0.5f, d_y2 = py + dy * 0.5f;

        const float iw = fmaxf(fminf(g_x2, d_x2) - fmaxf(g_x1, d_x1), 0.0f);
        const float ih = fmaxf(fminf(g_y2, d_y2) - fmaxf(g_y1, d_y1), 0.0f);
        const float inter = iw * ih;

        const float w1 = g_x2 - g_x1, h1 = g_y2 - g_y1;
        const float w2 = d_x2 - d_x1, h2 = d_y2 - d_y1;
        const float uni = w1 * h1 + 1e-16f + w2 * h2 - inter;

        loss = 1.0f - inter / uni;
    }

    // ── block reduction (deterministic fixed order) ──
    #pragma unroll
    for (int off = 16; off > 0; off >>= 1) {
        loss += __shfl_down_sync(0xFFFFFFFFu, loss, off);
        m    += __shfl_down_sync(0xFFFFFFFFu, m,    off);
    }

    __shared__ float s_sum[NN / 32];
    __shared__ int   s_cnt[NN / 32];
    __shared__ int   s_last;
    const int lane = n & 31, warp = n >> 5;
    if (lane == 0) { s_sum[warp] = loss; s_cnt[warp] = m; }
    __syncthreads();

    if (n == 0) {
        float v = 0.0f; int c = 0;
        #pragma unroll
        for (int i = 0; i < NN / 32; i++) { v += s_sum[i]; c += s_cnt[i]; }
        g_partial_sum[b] = v;
        g_partial_cnt[b] = c;
        __threadfence();                       // publish partials
        int ticket = atomicAdd(&g_arrive, 1);  // arrival counter
        s_last = (ticket == BB - 1) ? 1 : 0;
    }
    __syncthreads();

    // ── last block reduces all 128 partials in fixed order ──
    if (s_last) {
        float v = 0.0f; int c = 0;
        if (n < BB) {
            // bypass L1 to see other SMs' stores
            v = __ldcg(&g_partial_sum[n]);
            c = __ldcg(&g_partial_cnt[n]);
        }
        #pragma unroll
        for (int off = 16; off > 0; off >>= 1) {
            v += __shfl_down_sync(0xFFFFFFFFu, v, off);
            c += __shfl_down_sync(0xFFFFFFFFu, c, off);
        }
        __shared__ float f_sum[4];
        __shared__ int   f_cnt[4];
        if (n < BB && lane == 0) { f_sum[warp] = v; f_cnt[warp] = c; }
        __syncthreads();
        if (n == 0) {
            float total = f_sum[0] + f_sum[1] + f_sum[2] + f_sum[3];
            int   cnt   = f_cnt[0] + f_cnt[1] + f_cnt[2] + f_cnt[3];
            d_out[0] = total / (4.0f * (float)cnt + 0.0001f);
            g_arrive = 0;                      // reset for next graph replay
        }
    }
}

extern "C" void kernel_launch(void* const* d_in, const int* in_sizes, int n_in,
                              void* d_out, int out_size)
{
    const float* out_map = (const float*)d_in[0];  // [128,2,256,256] f32
    const float* target  = (const float*)d_in[1];  // [128,256,2]     f32
    const int*   ind     = (const int*)  d_in[2];  // [128,256]       i32
    const int*   mask    = (const int*)  d_in[3];  // [128,256]       i32 (bool)
    float*       outp    = (float*)d_out;

    iou_loss_fused<<<BB, NN>>>(out_map, target, ind, mask, outp);
}